// round 1
// baseline (speedup 1.0000x reference)
#include <cuda_runtime.h>
#include <cstdint>

#define B_   16
#define P_   784
#define D_   10000
#define LVL_ 256
#define NPAIR 157        // ceil(ceil(D/32)/2) word-pairs, 64 columns per block
#define NCHUNK 8
#define PCH  98          // P_ / NCHUNK

__device__ __forceinline__ unsigned maj3(unsigned a, unsigned b, unsigned c) {
    return (a & b) | (a & c) | (b & c);   // single LOP3
}

__global__ __launch_bounds__(256, 2)
void hdc_encode_kernel(const float* __restrict__ x,
                       const float* __restrict__ pw,
                       const float* __restrict__ vw,
                       float* __restrict__ out)
{
    __shared__ unsigned       vw_s[LVL_ * 2];          // bit-packed vw slice (2 words)
    __shared__ unsigned char  idx_s[16 * 788];         // padded pitch 788 (conflict-free)
    __shared__ unsigned short part[NCHUNK][16][68];    // per-chunk partial counts, padded

    const int t    = threadIdx.x;
    const int wp   = blockIdx.x;       // word-pair -> columns [wp*64, wp*64+64)
    const int warp = t >> 5;           // warp == p-chunk
    const int lane = t & 31;

    // ---- stage quantized level indices from x (exact: rn == round-half-even) ----
    for (int i = t; i < B_ * P_; i += 256) {
        int b = i / P_, p = i - b * P_;
        int q = __float2int_rn(x[i] * 255.0f);
        q = max(0, min(255, q));
        idx_s[b * 788 + p] = (unsigned char)q;
    }

    // ---- bit-pack this block's vw slice: 256 levels x 2 words ----
    for (int i = warp; i < LVL_ * 2; i += 8) {
        int lev = i >> 1, ws2 = i & 1;
        int col = wp * 64 + ws2 * 32 + lane;
        float v = (col < D_) ? vw[lev * D_ + col] : 1.0f;
        unsigned m = __ballot_sync(0xffffffffu, v < 0.0f);
        if (lane == 0) vw_s[i] = m;
    }
    __syncthreads();

    // ---- accumulate: thread = (batch b, word ws) for p in this warp's chunk ----
    const int  b   = lane & 15;
    const int  ws  = lane >> 4;
    const int  c0  = wp * 64 + lane;          // pw column for first ballot load
    const bool ok0 = (c0 < D_);
    const bool ok1 = (c0 + 32 < D_);
    const unsigned char* idxrow = idx_s + b * 788 + warp * PCH;
    const float* pwbase = pw + (size_t)(warp * PCH) * D_;

    unsigned cc0 = 0, cc1 = 0, cc2 = 0, cc3 = 0, cc4 = 0, cc5 = 0, cc6 = 0;

    #pragma unroll 1
    for (int g = 0; g < PCH / 7; g++) {       // 14 groups of 7 positions
        unsigned s[7];
        #pragma unroll
        for (int j = 0; j < 7; j++) {
            int pp = g * 7 + j;
            const float* row = pwbase + (size_t)pp * D_;
            float v0 = ok0 ? __ldg(row + c0)      : 1.0f;
            float v1 = ok1 ? __ldg(row + c0 + 32) : 1.0f;
            unsigned m0 = __ballot_sync(0xffffffffu, v0 < 0.0f);
            unsigned m1 = __ballot_sync(0xffffffffu, v1 < 0.0f);
            unsigned mpw = ws ? m1 : m0;
            unsigned lev = idxrow[pp];
            s[j] = vw_s[lev * 2 + ws] ^ mpw;  // bit=1 -> product negative
        }
        // CSA tree: 7 one-bit planes -> 3-bit value (b0 + 2*b1 + 4*b2)
        unsigned t1s = s[0] ^ s[1] ^ s[2], t1c = maj3(s[0], s[1], s[2]);
        unsigned t2s = s[3] ^ s[4] ^ s[5], t2c = maj3(s[3], s[4], s[5]);
        unsigned b0  = t1s ^ t2s ^ s[6],   t3c = maj3(t1s, t2s, s[6]);
        unsigned b1  = t1c ^ t2c ^ t3c;
        unsigned b2  = maj3(t1c, t2c, t3c);
        // add into 7-plane bit-sliced counter (max 98 < 128)
        unsigned cr  = cc0 & b0;  cc0 ^= b0;
        unsigned x1  = cc1 ^ b1;  unsigned cr1 = (cc1 & b1) | (x1 & cr);  cc1 = x1 ^ cr;
        unsigned x2  = cc2 ^ b2;  unsigned cr2 = (cc2 & b2) | (x2 & cr1); cc2 = x2 ^ cr1;
        unsigned tmp;
        tmp = cc3 & cr2; cc3 ^= cr2; cr2 = tmp;
        tmp = cc4 & cr2; cc4 ^= cr2; cr2 = tmp;
        tmp = cc5 & cr2; cc5 ^= cr2; cr2 = tmp;
        cc6 ^= cr2;
    }

    // ---- extract 32 per-column counts from the bit planes ----
    {
        unsigned short* prow = &part[warp][b][ws * 32];
        #pragma unroll
        for (int j = 0; j < 32; j++) {
            unsigned cnt = ((cc0 >> j) & 1u)
                         + (((cc1 >> j) & 1u) << 1)
                         + (((cc2 >> j) & 1u) << 2)
                         + (((cc3 >> j) & 1u) << 3)
                         + (((cc4 >> j) & 1u) << 4)
                         + (((cc5 >> j) & 1u) << 5)
                         + (((cc6 >> j) & 1u) << 6);
            prow[j] = (unsigned short)cnt;
        }
    }
    __syncthreads();

    // ---- reduce 8 chunks, compute sign, store ----
    {
        const int bb   = t >> 4;       // batch
        const int c4   = t & 15;       // group of 4 columns
        const int base = bb * 68 + c4 * 4;
        unsigned cnt0 = 0, cnt1 = 0, cnt2 = 0, cnt3 = 0;
        #pragma unroll
        for (int ch = 0; ch < NCHUNK; ch++) {
            const unsigned short* q = &part[ch][0][0] + base;
            cnt0 += q[0]; cnt1 += q[1]; cnt2 += q[2]; cnt3 += q[3];
        }
        // s = P - 2*cnt ; s > 0  <=>  cnt < P/2  (cnt == 392 -> s == 0 -> -1)
        const int gcol = wp * 64 + c4 * 4;
        float r0 = (cnt0 < (P_ / 2)) ? 1.0f : -1.0f;
        float r1 = (cnt1 < (P_ / 2)) ? 1.0f : -1.0f;
        float r2 = (cnt2 < (P_ / 2)) ? 1.0f : -1.0f;
        float r3 = (cnt3 < (P_ / 2)) ? 1.0f : -1.0f;
        float* orow = out + (size_t)bb * D_ + gcol;
        if (gcol + 3 < D_) {
            float4 r4 = make_float4(r0, r1, r2, r3);
            *reinterpret_cast<float4*>(orow) = r4;
        } else {
            if (gcol + 0 < D_) orow[0] = r0;
            if (gcol + 1 < D_) orow[1] = r1;
            if (gcol + 2 < D_) orow[2] = r2;
            if (gcol + 3 < D_) orow[3] = r3;
        }
    }
}

extern "C" void kernel_launch(void* const* d_in, const int* in_sizes, int n_in,
                              void* d_out, int out_size)
{
    (void)in_sizes; (void)n_in; (void)out_size;
    const float* x  = (const float*)d_in[0];   // (16, 28, 28)
    const float* pw = (const float*)d_in[1];   // (784, 10000)
    const float* vw = (const float*)d_in[2];   // (256, 10000)
    float* out = (float*)d_out;                // (16, 10000)
    hdc_encode_kernel<<<NPAIR, 256>>>(x, pw, vw, out);
}

// round 3
// speedup vs baseline: 1.6982x; 1.6982x over previous
#include <cuda_runtime.h>
#include <cstdint>

#define B_    16
#define P_    784
#define D_    10000
#define NW_   316          // full packed words per row: 79 groups x 4 (permuted layout)
#define NPAIR 158          // word-pairs processed by K2/K3
#define ROWP_ 320          // padded words per packed row
#define NROW_ 1040         // 784 pw rows + 256 vw rows
#define NSPL_ 4            // p splits in K2
#define PCHK_ 196          // P_/NSPL_
#define PITCH 197          // idx smem pitch (conflict-free)

// ---- device scratch (no allocations allowed) ----
__device__ unsigned g_pack[NROW_ * ROWP_];            // packed sign bits [row][word]
__device__ unsigned g_idx8[B_ * P_];                  // level index * 8 (byte offset)
__device__ unsigned g_part[NPAIR * NSPL_ * 128 * 8];  // per-thread 6-plane partials (pad 8)

__device__ __forceinline__ unsigned maj3(unsigned a, unsigned b, unsigned c) {
    return (a & b) | (a & c) | (b & c);   // single LOP3
}

// ============ K1: pack sign bits of pw/vw, quantize x ============
// Word W of a row: bit l  <->  column 128*(W>>2) + 4*l + (W&3)   (float4 ballot order)
__global__ __launch_bounds__(256)
void k_pack(const float* __restrict__ x,
            const float* __restrict__ pw,
            const float* __restrict__ vw)
{
    int bid = blockIdx.x;
    if (bid < NROW_) {
        const float* src = (bid < P_) ? (pw + (size_t)bid * D_)
                                      : (vw + (size_t)(bid - P_) * D_);
        int wid = threadIdx.x >> 5, lane = threadIdx.x & 31;
        for (int g = wid; g < 79; g += 8) {
            int col = g * 128 + lane * 4;
            float4 f;
            if (col + 3 < D_) f = *reinterpret_cast<const float4*>(src + col);
            else              f = make_float4(1.f, 1.f, 1.f, 1.f);
            unsigned m0 = __ballot_sync(0xffffffffu, f.x < 0.f);
            unsigned m1 = __ballot_sync(0xffffffffu, f.y < 0.f);
            unsigned m2 = __ballot_sync(0xffffffffu, f.z < 0.f);
            unsigned m3 = __ballot_sync(0xffffffffu, f.w < 0.f);
            if (lane == 0)
                *reinterpret_cast<uint4*>(&g_pack[bid * ROWP_ + g * 4]) =
                    make_uint4(m0, m1, m2, m3);
        }
    } else {
        int i = (bid - NROW_) * 256 + threadIdx.x;
        if (i < B_ * P_) {
            int q = __float2int_rn(x[i] * 255.0f);     // matches jnp.round (RN-even)
            q = max(0, min(255, q));
            g_idx8[i] = (unsigned)q * 8u;              // byte offset into vw_s
        }
    }
}

// ============ K2: bit-sliced accumulation over packed data ============
__global__ __launch_bounds__(128)
void k_acc()
{
    __shared__ unsigned vw_s[512];            // 256 levels x 2 words
    __shared__ unsigned ppw_s[PCHK_ * 2];     // 196 p x 2 words
    __shared__ unsigned idx_s[B_ * PITCH];    // level*8 per (b,p)

    const int wp = blockIdx.x;                // word pair -> words wp*2, wp*2+1
    const int sp = blockIdx.y;                // p split
    const int t  = threadIdx.x;
    const int wid = t >> 5, lane = t & 31;
    const int p0 = sp * PCHK_;

    for (int i = t; i < 512; i += 128)
        vw_s[i] = g_pack[(P_ + (i >> 1)) * ROWP_ + wp * 2 + (i & 1)];
    for (int i = t; i < PCHK_ * 2; i += 128)
        ppw_s[i] = g_pack[(p0 + (i >> 1)) * ROWP_ + wp * 2 + (i & 1)];
    for (int i = t; i < B_ * PCHK_; i += 128) {
        int b = i / PCHK_, p = i - b * PCHK_;
        idx_s[b * PITCH + p] = g_idx8[b * P_ + p0 + p];
    }
    __syncthreads();

    const int b  = lane & 15;
    const int ws = lane >> 4;
    const int pbase = wid * 49;               // 4 warps x 49 p = 196
    const unsigned* idxr = idx_s + b * PITCH + pbase;
    const unsigned* ppwr = ppw_s + pbase * 2 + ws;
    const char* vwb = reinterpret_cast<const char*>(vw_s) + ws * 4;

    unsigned cc0 = 0, cc1 = 0, cc2 = 0, cc3 = 0, cc4 = 0, cc5 = 0;

    #pragma unroll
    for (int g = 0; g < 7; g++) {
        unsigned s[7];
        #pragma unroll
        for (int j = 0; j < 7; j++) {
            unsigned lev8 = idxr[g * 7 + j];
            unsigned v = *reinterpret_cast<const unsigned*>(vwb + lev8);
            s[j] = v ^ ppwr[(g * 7 + j) * 2];
        }
        // CSA: 7 masks -> 3-bit (q0 + 2*q1 + 4*q2)
        unsigned t1s = s[0] ^ s[1] ^ s[2], t1c = maj3(s[0], s[1], s[2]);
        unsigned t2s = s[3] ^ s[4] ^ s[5], t2c = maj3(s[3], s[4], s[5]);
        unsigned q0  = t1s ^ t2s ^ s[6],   t3c = maj3(t1s, t2s, s[6]);
        unsigned q1  = t1c ^ t2c ^ t3c;
        unsigned q2  = maj3(t1c, t2c, t3c);
        // add 3-bit into 6-plane counter (max 49 -> no overflow)
        unsigned c = cc0 & q0;              cc0 ^= q0;
        unsigned n1 = maj3(cc1, q1, c);     cc1 = cc1 ^ q1 ^ c;  c = n1;
        unsigned n2 = maj3(cc2, q2, c);     cc2 = cc2 ^ q2 ^ c;  c = n2;
        unsigned n3 = cc3 & c;              cc3 ^= c;            c = n3;
        unsigned n4 = cc4 & c;              cc4 ^= c;            c = n4;
        cc5 ^= c;
    }

    unsigned* dst = g_part + (size_t)(((wp * NSPL_ + sp) * 128) + t) * 8;
    *reinterpret_cast<uint4*>(dst)     = make_uint4(cc0, cc1, cc2, cc3);
    *reinterpret_cast<uint2*>(dst + 4) = make_uint2(cc4, cc5);
}

// ============ K3: combine 16 partials, compare to 392 bit-sliced, sign ============
__global__ __launch_bounds__(128)
void k_fin(float* __restrict__ out)
{
    int u = blockIdx.x * 128 + threadIdx.x;
    if (u >= B_ * NW_) return;
    int b = u / NW_, w = u - b * NW_;
    int wp = w >> 1, ws = w & 1;
    int lanei = ws * 16 + b;

    unsigned P0=0,P1=0,P2=0,P3=0,P4=0,P5=0,P6=0,P7=0,P8=0,P9=0;
    #pragma unroll
    for (int k = 0; k < 16; k++) {
        int sp = k >> 2, warp = k & 3;
        const unsigned* src = g_part +
            (size_t)(((wp * NSPL_ + sp) * 128) + warp * 32 + lanei) * 8;
        uint4 a = *reinterpret_cast<const uint4*>(src);
        uint2 a2 = *reinterpret_cast<const uint2*>(src + 4);
        unsigned c, n;
        c = P0 & a.x;            P0 ^= a.x;
        n = maj3(P1, a.y, c);    P1 = P1 ^ a.y ^ c;   c = n;
        n = maj3(P2, a.z, c);    P2 = P2 ^ a.z ^ c;   c = n;
        n = maj3(P3, a.w, c);    P3 = P3 ^ a.w ^ c;   c = n;
        n = maj3(P4, a2.x, c);   P4 = P4 ^ a2.x ^ c;  c = n;
        n = maj3(P5, a2.y, c);   P5 = P5 ^ a2.y ^ c;  c = n;
        n = P6 & c;  P6 ^= c;  c = n;
        n = P7 & c;  P7 ^= c;  c = n;
        n = P8 & c;  P8 ^= c;  c = n;
        P9 ^= c;
    }

    // bit-sliced compare: borrow of (cnt - 392), 392 = 0b110001000 (bits 3,7,8)
    // K bit = 0: br' = ~a & br ; K bit = 1: br' = ~a | br
    unsigned br = 0;
    br = ~P0 & br;  br = ~P1 & br;  br = ~P2 & br;
    br = ~P3 | br;                                  // bit 3 set
    br = ~P4 & br;  br = ~P5 & br;  br = ~P6 & br;
    br = ~P7 | br;  br = ~P8 | br;                  // bits 7,8 set
    br = ~P9 & br;
    // br bit l == 1  <=>  cnt_l < 392  <=>  output +1

    int colbase = 128 * (w >> 2) + (w & 3);
    float* orow = out + (size_t)b * D_;
    #pragma unroll
    for (int j = 0; j < 32; j++) {
        int col = colbase + 4 * j;
        if (col < D_) {
            unsigned sgn = ((br >> j) & 1u) ^ 1u;   // 0 -> +1.0f, 1 -> -1.0f
            orow[col] = __uint_as_float(0x3F800000u | (sgn << 31));
        }
    }
}

extern "C" void kernel_launch(void* const* d_in, const int* in_sizes, int n_in,
                              void* d_out, int out_size)
{
    (void)in_sizes; (void)n_in; (void)out_size;
    const float* x  = (const float*)d_in[0];   // (16, 28, 28)
    const float* pw = (const float*)d_in[1];   // (784, 10000)
    const float* vw = (const float*)d_in[2];   // (256, 10000)
    float* out = (float*)d_out;                // (16, 10000)

    k_pack<<<NROW_ + 49, 256>>>(x, pw, vw);
    k_acc<<<dim3(NPAIR, NSPL_), 128>>>();
    k_fin<<<(B_ * NW_ + 127) / 128, 128>>>(out);
}

// round 4
// speedup vs baseline: 2.0350x; 1.1983x over previous
#include <cuda_runtime.h>
#include <cstdint>

#define B_    16
#define P_    784
#define D_    10000
#define NW_   316          // packed words per row: 79 groups x 4 (permuted ballot layout)
#define NROW_ 1040         // 784 pw rows + 256 vw rows
#define NXB_  25           // extra blocks for x quantize (512 thr each)

// ---- device scratch ----
__device__ unsigned g_packT[NW_ * NROW_];   // TRANSPOSED: [word][row]  (1.31 MB)
__device__ unsigned g_idxw[B_ * P_ / 4];    // level indices, byte-packed (u32 view)

__device__ __forceinline__ unsigned maj3(unsigned a, unsigned b, unsigned c) {
    return (a & b) | (a & c) | (b & c);   // single LOP3
}

// ============ K1: pack sign bits (transposed), quantize x ============
// Word W: bit l <-> column 128*(W>>2) + 4*l + (W&3)
__global__ __launch_bounds__(512)
void k_pack(const float* __restrict__ x,
            const float* __restrict__ pw,
            const float* __restrict__ vw)
{
    int bid = blockIdx.x;
    if (bid < NROW_) {
        const float* src = (bid < P_) ? (pw + (size_t)bid * D_)
                                      : (vw + (size_t)(bid - P_) * D_);
        int wid = threadIdx.x >> 5, lane = threadIdx.x & 31;

        // batch 5 independent loads -> MLP=5 per thread
        float4 f[5];
        #pragma unroll
        for (int k = 0; k < 5; k++) {
            int g   = wid + k * 16;           // groups 0..79 covered once (g=79 skipped)
            int col = g * 128 + lane * 4;
            bool ok = (g < 79) && (col + 3 < D_);
            f[k] = ok ? *reinterpret_cast<const float4*>(src + col)
                      : make_float4(1.f, 1.f, 1.f, 1.f);
        }
        #pragma unroll
        for (int k = 0; k < 5; k++) {
            int g = wid + k * 16;
            if (g < 79) {                       // warp-uniform
                unsigned m0 = __ballot_sync(0xffffffffu, f[k].x < 0.f);
                unsigned m1 = __ballot_sync(0xffffffffu, f[k].y < 0.f);
                unsigned m2 = __ballot_sync(0xffffffffu, f[k].z < 0.f);
                unsigned m3 = __ballot_sync(0xffffffffu, f[k].w < 0.f);
                if (lane < 4) {
                    unsigned mm = (lane == 0) ? m0 : (lane == 1) ? m1
                                 : (lane == 2) ? m2 : m3;
                    g_packT[(size_t)(g * 4 + lane) * NROW_ + bid] = mm;
                }
            }
        }
    } else {
        int i = (bid - NROW_) * 512 + threadIdx.x;
        if (i < B_ * P_) {
            int q = __float2int_rn(x[i] * 255.0f);   // matches jnp.round (RN-even)
            q = max(0, min(255, q));
            reinterpret_cast<unsigned char*>(g_idxw)[i] = (unsigned char)q;
        }
    }
}

// ============ K2 (fused): accumulate + combine + compare + store ============
// One block per word (316 blocks x 256 threads). 16 p-chunks of 49.
__global__ __launch_bounds__(256)
void k_acc(float* __restrict__ out)
{
    __shared__ unsigned vw_s[256];             // packed vw bits for this word
    __shared__ unsigned ppw_s[P_];             // packed pw bits for this word
    __shared__ unsigned idx4[B_ * 197];        // level bytes, pitch 788B (conflict-free)
    __shared__ unsigned part[16][16][7];       // [chunk][b][6 planes] (pad 7)
    __shared__ unsigned br_s[16];

    const int w   = blockIdx.x;
    const int t   = threadIdx.x;
    const int wid = t >> 5, lane = t & 31;
    const unsigned char* idx_b = reinterpret_cast<const unsigned char*>(idx4);

    // coalesced smem fills from transposed pack
    const unsigned* colbase = g_packT + (size_t)w * NROW_;
    for (int i = t; i < P_; i += 256)  ppw_s[i] = colbase[i];
    if (t < 256)                       vw_s[t]  = colbase[P_ + t];
    for (int i = t; i < B_ * 196; i += 256) {
        int b = i / 196, j = i - b * 196;
        idx4[b * 197 + j] = g_idxw[i];
    }
    __syncthreads();

    // thread = (chunk, b): chunk = wid*2 + ph, 49 positions each
    const int b  = lane & 15;
    const int ph = lane >> 4;
    const int ch = wid * 2 + ph;
    const int pbase = ch * 49;
    const unsigned char* idxr = idx_b + b * 788 + pbase;
    const unsigned* ppwr = ppw_s + pbase;

    unsigned cc0 = 0, cc1 = 0, cc2 = 0, cc3 = 0, cc4 = 0, cc5 = 0;
    #pragma unroll
    for (int g = 0; g < 7; g++) {
        unsigned s[7];
        #pragma unroll
        for (int j = 0; j < 7; j++) {
            unsigned lev = idxr[g * 7 + j];
            s[j] = vw_s[lev] ^ ppwr[g * 7 + j];
        }
        unsigned t1s = s[0] ^ s[1] ^ s[2], t1c = maj3(s[0], s[1], s[2]);
        unsigned t2s = s[3] ^ s[4] ^ s[5], t2c = maj3(s[3], s[4], s[5]);
        unsigned q0  = t1s ^ t2s ^ s[6],   t3c = maj3(t1s, t2s, s[6]);
        unsigned q1  = t1c ^ t2c ^ t3c;
        unsigned q2  = maj3(t1c, t2c, t3c);
        unsigned c = cc0 & q0;            cc0 ^= q0;
        unsigned n1 = maj3(cc1, q1, c);   cc1 = cc1 ^ q1 ^ c;  c = n1;
        unsigned n2 = maj3(cc2, q2, c);   cc2 = cc2 ^ q2 ^ c;  c = n2;
        unsigned n3 = cc3 & c;            cc3 ^= c;            c = n3;
        unsigned n4 = cc4 & c;            cc4 ^= c;            c = n4;
        cc5 ^= c;                                              // max 49 < 64
    }
    part[ch][b][0] = cc0; part[ch][b][1] = cc1; part[ch][b][2] = cc2;
    part[ch][b][3] = cc3; part[ch][b][4] = cc4; part[ch][b][5] = cc5;
    __syncthreads();

    // threads 0..15: combine 16 chunks bit-sliced -> 10 planes, compare vs 392
    if (t < 16) {
        unsigned P0=0,P1=0,P2=0,P3=0,P4=0,P5=0,P6=0,P7=0,P8=0,P9=0;
        #pragma unroll
        for (int k = 0; k < 16; k++) {
            const unsigned* a = part[k][t];
            unsigned c, n;
            c = P0 & a[0];           P0 ^= a[0];
            n = maj3(P1, a[1], c);   P1 = P1 ^ a[1] ^ c;  c = n;
            n = maj3(P2, a[2], c);   P2 = P2 ^ a[2] ^ c;  c = n;
            n = maj3(P3, a[3], c);   P3 = P3 ^ a[3] ^ c;  c = n;
            n = maj3(P4, a[4], c);   P4 = P4 ^ a[4] ^ c;  c = n;
            n = maj3(P5, a[5], c);   P5 = P5 ^ a[5] ^ c;  c = n;
            n = P6 & c;  P6 ^= c;  c = n;
            n = P7 & c;  P7 ^= c;  c = n;
            n = P8 & c;  P8 ^= c;  c = n;
            P9 ^= c;                                        // max 784 < 1024
        }
        // borrow of (cnt - 392); 392 = bits 3,7,8.  br=1 <=> cnt<392 <=> +1
        unsigned br = 0;
        br = ~P0 & br;  br = ~P1 & br;  br = ~P2 & br;
        br = ~P3 | br;
        br = ~P4 & br;  br = ~P5 & br;  br = ~P6 & br;
        br = ~P7 | br;  br = ~P8 | br;
        br = ~P9 & br;
        br_s[t] = br;
    }
    __syncthreads();

    // store: 512 signs (16 b x 32 bits), 2 per thread
    {
        int bb = t >> 4;
        int j0 = (t & 15) * 2;
        unsigned br = br_s[bb];
        int cb = 128 * (w >> 2) + (w & 3);
        float* orow = out + (size_t)bb * D_;
        #pragma unroll
        for (int q = 0; q < 2; q++) {
            int j = j0 + q;
            int col = cb + 4 * j;
            if (col < D_) {
                unsigned sgn = ((br >> j) & 1u) ^ 1u;
                orow[col] = __uint_as_float(0x3F800000u | (sgn << 31));
            }
        }
    }
}

extern "C" void kernel_launch(void* const* d_in, const int* in_sizes, int n_in,
                              void* d_out, int out_size)
{
    (void)in_sizes; (void)n_in; (void)out_size;
    const float* x  = (const float*)d_in[0];   // (16, 28, 28)
    const float* pw = (const float*)d_in[1];   // (784, 10000)
    const float* vw = (const float*)d_in[2];   // (256, 10000)
    float* out = (float*)d_out;                // (16, 10000)

    k_pack<<<NROW_ + NXB_, 512>>>(x, pw, vw);
    k_acc<<<NW_, 256>>>(out);
}

// round 5
// speedup vs baseline: 2.3169x; 1.1385x over previous
#include <cuda_runtime.h>
#include <cstdint>

#define B_    16
#define P_    784
#define D_    10000
#define NW_   316          // packed words per row: 79 groups x 4 (permuted ballot layout)
#define NROW_ 1040         // 784 pw rows + 256 vw rows
#define NXB_  25           // extra blocks for x quantize (512 thr each)

// ---- device scratch ----
__device__ unsigned g_packT[NW_ * NROW_];   // TRANSPOSED: [word][row]  (1.31 MB)
__device__ unsigned g_idxr[16 * 16 * 16];   // level bytes [ch][b][64B pitch] (16 KB)

__device__ __forceinline__ unsigned maj3(unsigned a, unsigned b, unsigned c) {
    return (a & b) | (a & c) | (b & c);   // single LOP3
}

// ============ K1: pack sign bits (transposed), quantize x ============
// Word W: bit l <-> column 128*(W>>2) + 4*l + (W&3)
__global__ __launch_bounds__(512)
void k_pack(const float* __restrict__ x,
            const float* __restrict__ pw,
            const float* __restrict__ vw)
{
    int bid = blockIdx.x;
    if (bid < NROW_) {
        const float* src = (bid < P_) ? (pw + (size_t)bid * D_)
                                      : (vw + (size_t)(bid - P_) * D_);
        int wid = threadIdx.x >> 5, lane = threadIdx.x & 31;

        float4 f[5];                        // MLP=5 per thread
        #pragma unroll
        for (int k = 0; k < 5; k++) {
            int g   = wid + k * 16;
            int col = g * 128 + lane * 4;
            bool ok = (g < 79) && (col + 3 < D_);
            f[k] = ok ? *reinterpret_cast<const float4*>(src + col)
                      : make_float4(1.f, 1.f, 1.f, 1.f);
        }
        #pragma unroll
        for (int k = 0; k < 5; k++) {
            int g = wid + k * 16;
            if (g < 79) {                   // warp-uniform
                unsigned m0 = __ballot_sync(0xffffffffu, f[k].x < 0.f);
                unsigned m1 = __ballot_sync(0xffffffffu, f[k].y < 0.f);
                unsigned m2 = __ballot_sync(0xffffffffu, f[k].z < 0.f);
                unsigned m3 = __ballot_sync(0xffffffffu, f[k].w < 0.f);
                if (lane < 4) {
                    unsigned mm = (lane == 0) ? m0 : (lane == 1) ? m1
                                 : (lane == 2) ? m2 : m3;
                    g_packT[(size_t)(g * 4 + lane) * NROW_ + bid] = mm;
                }
            }
        }
    } else {
        int i = (bid - NROW_) * 512 + threadIdx.x;
        if (i < B_ * P_) {
            int b = i / P_, p = i - b * P_;
            int ch = p / 49, j = p - ch * 49;
            int q = __float2int_rn(x[i] * 255.0f);   // matches jnp.round (RN-even)
            q = max(0, min(255, q));
            reinterpret_cast<unsigned char*>(g_idxr)[((ch * 16 + b) << 6) + j] =
                (unsigned char)q;
        }
    }
}

// ============ K2 (fused): accumulate + combine + compare + store ============
// One block per word (316 blocks x 256 threads). 16 p-chunks of 49.
__global__ __launch_bounds__(256)
void k_acc(float* __restrict__ out)
{
    __shared__ unsigned vw_s[256];          // packed vw bits for this word (1 KB)
    __shared__ unsigned ppw_s[P_];          // packed pw bits for this word (3.1 KB)
    __shared__ unsigned part2[8][16][9];    // [warp][b][7 planes] pad 9 (4.6 KB)
    __shared__ unsigned br_s[16];

    const int w   = blockIdx.x;
    const int t   = threadIdx.x;
    const int wid = t >> 5, lane = t & 31;

    const unsigned* colbase = g_packT + (size_t)w * NROW_;
    for (int i = t; i < P_; i += 256)  ppw_s[i] = colbase[i];
    if (t < 256)                       vw_s[t]  = colbase[P_ + t];

    // thread = (b, chunk): 49 level bytes -> registers (4 vector LDGs, L1-hot)
    const int b  = lane & 15;
    const int ph = lane >> 4;
    const int ch = wid * 2 + ph;
    unsigned u[13];
    {
        const uint4* src = reinterpret_cast<const uint4*>(g_idxr + (ch * 16 + b) * 16);
        uint4 a0 = src[0], a1 = src[1], a2 = src[2];
        unsigned ex = g_idxr[(ch * 16 + b) * 16 + 12];
        u[0]=a0.x; u[1]=a0.y; u[2]=a0.z; u[3]=a0.w;
        u[4]=a1.x; u[5]=a1.y; u[6]=a1.z; u[7]=a1.w;
        u[8]=a2.x; u[9]=a2.y; u[10]=a2.z; u[11]=a2.w; u[12]=ex;
    }
    __syncthreads();

    const unsigned* ppwr = ppw_s + ch * 49;
    unsigned cc0 = 0, cc1 = 0, cc2 = 0, cc3 = 0, cc4 = 0, cc5 = 0;

    #pragma unroll
    for (int g = 0; g < 7; g++) {
        unsigned s[7];
        #pragma unroll
        for (int jj = 0; jj < 7; jj++) {
            int j = g * 7 + jj;                       // compile-time constant
            unsigned lev = (u[j >> 2] >> ((j & 3) * 8)) & 255u;
            s[jj] = vw_s[lev] ^ ppwr[j];              // ppw LDS is a broadcast
        }
        unsigned t1s = s[0] ^ s[1] ^ s[2], t1c = maj3(s[0], s[1], s[2]);
        unsigned t2s = s[3] ^ s[4] ^ s[5], t2c = maj3(s[3], s[4], s[5]);
        unsigned q0  = t1s ^ t2s ^ s[6],   t3c = maj3(t1s, t2s, s[6]);
        unsigned q1  = t1c ^ t2c ^ t3c;
        unsigned q2  = maj3(t1c, t2c, t3c);
        unsigned c = cc0 & q0;            cc0 ^= q0;
        unsigned n1 = maj3(cc1, q1, c);   cc1 = cc1 ^ q1 ^ c;  c = n1;
        unsigned n2 = maj3(cc2, q2, c);   cc2 = cc2 ^ q2 ^ c;  c = n2;
        unsigned n3 = cc3 & c;            cc3 ^= c;            c = n3;
        unsigned n4 = cc4 & c;            cc4 ^= c;            c = n4;
        cc5 ^= c;                                              // max 49 < 64
    }

    // combine chunk pair (lane ^ 16) via shuffle: 6+6 planes -> 7 planes (max 98)
    {
        unsigned d0 = __shfl_xor_sync(0xffffffffu, cc0, 16);
        unsigned d1 = __shfl_xor_sync(0xffffffffu, cc1, 16);
        unsigned d2 = __shfl_xor_sync(0xffffffffu, cc2, 16);
        unsigned d3 = __shfl_xor_sync(0xffffffffu, cc3, 16);
        unsigned d4 = __shfl_xor_sync(0xffffffffu, cc4, 16);
        unsigned d5 = __shfl_xor_sync(0xffffffffu, cc5, 16);
        unsigned c, n;
        c = cc0 & d0;            cc0 ^= d0;
        n = maj3(cc1, d1, c);    cc1 = cc1 ^ d1 ^ c;  c = n;
        n = maj3(cc2, d2, c);    cc2 = cc2 ^ d2 ^ c;  c = n;
        n = maj3(cc3, d3, c);    cc3 = cc3 ^ d3 ^ c;  c = n;
        n = maj3(cc4, d4, c);    cc4 = cc4 ^ d4 ^ c;  c = n;
        n = maj3(cc5, d5, c);    cc5 = cc5 ^ d5 ^ c;  c = n;
        if (lane < 16) {
            unsigned* pr = part2[wid][b];
            pr[0]=cc0; pr[1]=cc1; pr[2]=cc2; pr[3]=cc3; pr[4]=cc4; pr[5]=cc5; pr[6]=c;
        }
    }
    __syncthreads();

    // threads 0..15: combine 8 warps' 7-plane partials -> 10 planes, compare vs 392
    if (t < 16) {
        unsigned P0=0,P1=0,P2=0,P3=0,P4=0,P5=0,P6=0,P7=0,P8=0,P9=0;
        #pragma unroll
        for (int k = 0; k < 8; k++) {
            const unsigned* a = part2[k][t];
            unsigned c, n;
            c = P0 & a[0];           P0 ^= a[0];
            n = maj3(P1, a[1], c);   P1 = P1 ^ a[1] ^ c;  c = n;
            n = maj3(P2, a[2], c);   P2 = P2 ^ a[2] ^ c;  c = n;
            n = maj3(P3, a[3], c);   P3 = P3 ^ a[3] ^ c;  c = n;
            n = maj3(P4, a[4], c);   P4 = P4 ^ a[4] ^ c;  c = n;
            n = maj3(P5, a[5], c);   P5 = P5 ^ a[5] ^ c;  c = n;
            n = maj3(P6, a[6], c);   P6 = P6 ^ a[6] ^ c;  c = n;
            n = P7 & c;  P7 ^= c;  c = n;
            n = P8 & c;  P8 ^= c;  c = n;
            P9 ^= c;                                       // max 784 < 1024
        }
        // borrow of (cnt - 392); 392 = bits 3,7,8.  br=1 <=> cnt<392 <=> +1
        unsigned br = 0;
        br = ~P0 & br;  br = ~P1 & br;  br = ~P2 & br;
        br = ~P3 | br;
        br = ~P4 & br;  br = ~P5 & br;  br = ~P6 & br;
        br = ~P7 | br;  br = ~P8 | br;
        br = ~P9 & br;
        br_s[t] = br;
    }
    __syncthreads();

    // store: 512 signs (16 b x 32 bits), 2 per thread
    {
        int bb = t >> 4;
        int j0 = (t & 15) * 2;
        unsigned br = br_s[bb];
        int cb = 128 * (w >> 2) + (w & 3);
        float* orow = out + (size_t)bb * D_;
        #pragma unroll
        for (int q = 0; q < 2; q++) {
            int j = j0 + q;
            int col = cb + 4 * j;
            if (col < D_) {
                unsigned sgn = ((br >> j) & 1u) ^ 1u;
                orow[col] = __uint_as_float(0x3F800000u | (sgn << 31));
            }
        }
    }
}

extern "C" void kernel_launch(void* const* d_in, const int* in_sizes, int n_in,
                              void* d_out, int out_size)
{
    (void)in_sizes; (void)n_in; (void)out_size;
    const float* x  = (const float*)d_in[0];   // (16, 28, 28)
    const float* pw = (const float*)d_in[1];   // (784, 10000)
    const float* vw = (const float*)d_in[2];   // (256, 10000)
    float* out = (float*)d_out;                // (16, 10000)

    k_pack<<<NROW_ + NXB_, 512>>>(x, pw, vw);
    k_acc<<<NW_, 256>>>(out);
}